// round 2
// baseline (speedup 1.0000x reference)
#include <cuda_runtime.h>
#include <math.h>
#include <cstdint>

#define N_NODES 10000
#define N_EDGES 160000
#define FDIM 128
#define NRBD 32
#define PHI_DIM 1024

// scratch (static device globals: allocation-free)
__device__ float g_h[N_NODES * FDIM];       // silu(s@W1+b1)
__device__ float g_phi[N_NODES * PHI_DIM];  // phi

// ---------------- init: out = concat(s, v) ----------------
__global__ void init_out_kernel(const float* __restrict__ s,
                                const float* __restrict__ v,
                                float* __restrict__ out) {
    int ns4 = (N_NODES * FDIM) / 4;
    int nv4 = (N_NODES * 3 * FDIM) / 4;
    int total4 = ns4 + nv4;
    for (int t = blockIdx.x * blockDim.x + threadIdx.x; t < total4;
         t += gridDim.x * blockDim.x) {
        float4 val = (t < ns4) ? ((const float4*)s)[t]
                               : ((const float4*)v)[t - ns4];
        ((float4*)out)[t] = val;
    }
}

// ---------------- SGEMM: C = A[M,K] @ B[K,N] + bias, optional SiLU ----------
// BM=BN=64, BK=16, TM=TN=4, 256 threads. N % 64 == 0, K % 16 == 0 assumed.
template <bool SILU>
__global__ __launch_bounds__(256) void sgemm_kernel(
    const float* __restrict__ A, const float* __restrict__ B,
    const float* __restrict__ bias, float* __restrict__ C,
    int M, int N, int K) {
    __shared__ float As[16][68];  // transposed, padded
    __shared__ float Bs[16][64];

    int tid = threadIdx.x;
    int tx = tid % 16, ty = tid / 16;
    int bRow = blockIdx.y * 64, bCol = blockIdx.x * 64;
    int aRow = tid / 4, aCol = (tid % 4) * 4;
    int bRowL = tid / 16, bColL = (tid % 16) * 4;

    float acc[4][4] = {};

    for (int kt = 0; kt < K; kt += 16) {
        float4 a = make_float4(0.f, 0.f, 0.f, 0.f);
        int gRow = bRow + aRow;
        if (gRow < M) a = *(const float4*)(A + (size_t)gRow * K + kt + aCol);
        As[aCol + 0][aRow] = a.x;
        As[aCol + 1][aRow] = a.y;
        As[aCol + 2][aRow] = a.z;
        As[aCol + 3][aRow] = a.w;

        float4 b = *(const float4*)(B + (size_t)(kt + bRowL) * N + bCol + bColL);
        *(float4*)&Bs[bRowL][bColL] = b;
        __syncthreads();

#pragma unroll
        for (int k = 0; k < 16; ++k) {
            float rm[4];
#pragma unroll
            for (int i = 0; i < 4; i++) rm[i] = As[k][ty * 4 + i];
            float4 bn = *(float4*)&Bs[k][tx * 4];
            float rn[4] = {bn.x, bn.y, bn.z, bn.w};
#pragma unroll
            for (int i = 0; i < 4; i++)
#pragma unroll
                for (int j = 0; j < 4; j++) acc[i][j] += rm[i] * rn[j];
        }
        __syncthreads();
    }

#pragma unroll
    for (int i = 0; i < 4; i++) {
        int r = bRow + ty * 4 + i;
        if (r >= M) continue;
#pragma unroll
        for (int j = 0; j < 4; j++) {
            int c = bCol + tx * 4 + j;
            float val = acc[i][j] + bias[c];
            if (SILU) val = val / (1.0f + expf(-val));
            C[(size_t)r * N + c] = val;
        }
    }
}

// ---------------- fused edge kernel ----------------
// Per edge e:  rcomb = fc1*re1 + fc2*re2 + fc3*re3  (len 32)
//              W     = rcomb @ Wr + (fc1+fc2+fc3)*br  (len 1024)
//              x     = phi[j] * W   -> 8 chunks of 128
//              scatter-add into out_s[i], out_v[i] with unit-vector/cross math.
// 512 threads = 4 eslots x 128 features; each eslot register-blocks 8 edges.
// Wr resident in SMEM, split as two float4 arrays (chunks 0-3 / 4-7) so the
// per-feature LDS.128 is conflict-free.
__global__ __launch_bounds__(512, 1) void edge_kernel(
    const float* __restrict__ re1, const float* __restrict__ re2,
    const float* __restrict__ re3, const float* __restrict__ fc1,
    const float* __restrict__ fc2, const float* __restrict__ fc3,
    const float* __restrict__ uv1, const float* __restrict__ uv2,
    const float* __restrict__ uv3, const int* __restrict__ eidx,
    const float* __restrict__ Wr, const float* __restrict__ br,
    const float* __restrict__ v, float* __restrict__ out) {
    extern __shared__ float smem[];
    float4* wrA = (float4*)smem;         // [32*128] chunks 0..3
    float4* wrB = wrA + NRBD * FDIM;     // [32*128] chunks 4..7
    float4* rc4 = wrB + NRBD * FDIM;     // [32 edges][8]  (rcomb as float4)
    float* uvs = (float*)(rc4 + 32 * 8); // [32][9]
    float* fcs = uvs + 32 * 9;           // [32]
    int* iis = (int*)(fcs + 32);         // [32]
    int* jjs = iis + 32;                 // [32]

    int tid = threadIdx.x;

    // one-time Wr load into transposed/split SMEM layout
    for (int idx = tid; idx < NRBD * PHI_DIM; idx += 512) {
        int k = idx >> 10;
        int col = idx & 1023;
        int c = col >> 7, ff = col & 127;
        float val = Wr[idx];
        float* dst = (c < 4) ? (float*)&wrA[k * FDIM + ff]
                             : (float*)&wrB[k * FDIM + ff];
        dst[c & 3] = val;
    }

    int ff = tid & 127;
    int eslot = tid >> 7;

    float brc[8];
#pragma unroll
    for (int c = 0; c < 8; c++) brc[c] = br[c * FDIM + ff];

    float* out_s = out;
    float* out_v = out + (size_t)N_NODES * FDIM;

    const int numTiles = N_EDGES / 32;
    for (int tile = blockIdx.x; tile < numTiles; tile += gridDim.x) {
        __syncthreads();  // protect smem staging vs previous iteration readers
        int eBase = tile * 32;

        // stage rcomb (32 edges x 32 k)
        float* rcf = (float*)rc4;
        for (int idx = tid; idx < 32 * NRBD; idx += 512) {
            int e = idx >> 5, k = idx & 31;
            int ge = eBase + e;
            float r = re1[ge * NRBD + k] * fc1[ge] +
                      re2[ge * NRBD + k] * fc2[ge] +
                      re3[ge * NRBD + k] * fc3[ge];
            rcf[e * NRBD + k] = r;
        }
        // per-edge metadata
        if (tid < 32) {
            int ge = eBase + tid;
            iis[tid] = eidx[ge];
            jjs[tid] = eidx[N_EDGES + ge];
            fcs[tid] = fc1[ge] + fc2[ge] + fc3[ge];
#pragma unroll
            for (int d = 0; d < 3; d++) {
                uvs[tid * 9 + d] = uv1[ge * 3 + d];
                uvs[tid * 9 + 3 + d] = uv2[ge * 3 + d];
                uvs[tid * 9 + 6 + d] = uv3[ge * 3 + d];
            }
        }
        __syncthreads();

        // W accumulators for this thread's 8 edges x 8 chunks
        float acc[8][8];
#pragma unroll
        for (int e = 0; e < 8; e++) {
            float fs = fcs[eslot * 8 + e];
#pragma unroll
            for (int c = 0; c < 8; c++) acc[e][c] = fs * brc[c];
        }

#pragma unroll
        for (int kk = 0; kk < 8; ++kk) {
            float4 r[8];
#pragma unroll
            for (int e = 0; e < 8; e++) r[e] = rc4[(eslot * 8 + e) * 8 + kk];
#pragma unroll
            for (int d = 0; d < 4; ++d) {
                int k = kk * 4 + d;
                float4 a = wrA[k * FDIM + ff];
                float4 b = wrB[k * FDIM + ff];
#pragma unroll
                for (int e = 0; e < 8; e++) {
                    float rv = (d == 0) ? r[e].x
                             : (d == 1) ? r[e].y
                             : (d == 2) ? r[e].z
                                        : r[e].w;
                    acc[e][0] += rv * a.x;
                    acc[e][1] += rv * a.y;
                    acc[e][2] += rv * a.z;
                    acc[e][3] += rv * a.w;
                    acc[e][4] += rv * b.x;
                    acc[e][5] += rv * b.y;
                    acc[e][6] += rv * b.z;
                    acc[e][7] += rv * b.w;
                }
            }
        }

        // epilogue: gather phi/v, vector + cross math, scatter-add
#pragma unroll
        for (int e = 0; e < 8; e++) {
            int le = eslot * 8 + e;
            int i = iis[le], j = jjs[le];
            const float* pj = g_phi + (size_t)j * PHI_DIM + ff;
            float x0 = acc[e][0] * pj[0];
            float x1 = acc[e][1] * pj[128];
            float x2 = acc[e][2] * pj[256];
            float x3 = acc[e][3] * pj[384];
            float x4 = acc[e][4] * pj[512];
            float x5 = acc[e][5] * pj[640];
            float x6 = acc[e][6] * pj[768];
            float x7 = acc[e][7] * pj[896];

            const float* vj = v + (size_t)j * (3 * FDIM) + ff;
            float v0 = vj[0], v1 = vj[128], v2 = vj[256];

            float u1x = uvs[le * 9 + 0], u1y = uvs[le * 9 + 1], u1z = uvs[le * 9 + 2];
            float u2x = uvs[le * 9 + 3], u2y = uvs[le * 9 + 4], u2z = uvs[le * 9 + 5];
            float u3x = uvs[le * 9 + 6], u3y = uvs[le * 9 + 7], u3z = uvs[le * 9 + 8];

            // cross(vj, u) = (v1*uz - v2*uy, v2*ux - v0*uz, v0*uy - v1*ux)
            float xv0 = v0 * x1 + x2 * u1x + x3 * u2x + x4 * u3x +
                        x5 * (v1 * u1z - v2 * u1y) +
                        x6 * (v1 * u2z - v2 * u2y) +
                        x7 * (v1 * u3z - v2 * u3y);
            float xv1 = v1 * x1 + x2 * u1y + x3 * u2y + x4 * u3y +
                        x5 * (v2 * u1x - v0 * u1z) +
                        x6 * (v2 * u2x - v0 * u2z) +
                        x7 * (v2 * u3x - v0 * u3z);
            float xv2 = v2 * x1 + x2 * u1z + x3 * u2z + x4 * u3z +
                        x5 * (v0 * u1y - v1 * u1x) +
                        x6 * (v0 * u2y - v1 * u2x) +
                        x7 * (v0 * u3y - v1 * u3x);

            atomicAdd(out_s + (size_t)i * FDIM + ff, x0);
            float* ov = out_v + (size_t)i * (3 * FDIM) + ff;
            atomicAdd(ov, xv0);
            atomicAdd(ov + 128, xv1);
            atomicAdd(ov + 256, xv2);
        }
    }
}

// ---------------- host ----------------
extern "C" void kernel_launch(void* const* d_in, const int* in_sizes, int n_in,
                              void* d_out, int out_size) {
    const float* s = (const float*)d_in[0];
    const float* v = (const float*)d_in[1];
    const float* re1 = (const float*)d_in[2];
    const float* re2 = (const float*)d_in[3];
    const float* re3 = (const float*)d_in[4];
    const float* fc1 = (const float*)d_in[5];
    const float* fc2 = (const float*)d_in[6];
    const float* fc3 = (const float*)d_in[7];
    const float* uv1 = (const float*)d_in[8];
    const float* uv2 = (const float*)d_in[9];
    const float* uv3 = (const float*)d_in[10];
    const int* eidx = (const int*)d_in[11];
    const float* W1 = (const float*)d_in[12];
    const float* b1 = (const float*)d_in[13];
    const float* W2 = (const float*)d_in[14];
    const float* b2 = (const float*)d_in[15];
    const float* Wr = (const float*)d_in[16];
    const float* br = (const float*)d_in[17];
    float* out = (float*)d_out;

    float *hptr, *phiptr;
    cudaGetSymbolAddress((void**)&hptr, g_h);
    cudaGetSymbolAddress((void**)&phiptr, g_phi);

    init_out_kernel<<<256, 256>>>(s, v, out);

    dim3 g1(FDIM / 64, (N_NODES + 63) / 64);
    sgemm_kernel<true><<<g1, 256>>>(s, W1, b1, hptr, N_NODES, FDIM, FDIM);

    dim3 g2(PHI_DIM / 64, (N_NODES + 63) / 64);
    sgemm_kernel<false><<<g2, 256>>>(hptr, W2, b2, phiptr, N_NODES, PHI_DIM, FDIM);

    int smem_bytes = (NRBD * FDIM * 2 + 32 * 8) * (int)sizeof(float4) +
                     (32 * 9 + 32) * (int)sizeof(float) + 32 * 2 * (int)sizeof(int);
    cudaFuncSetAttribute(edge_kernel,
                         cudaFuncAttributeMaxDynamicSharedMemorySize, smem_bytes);
    edge_kernel<<<148, 512, smem_bytes>>>(re1, re2, re3, fc1, fc2, fc3, uv1, uv2,
                                          uv3, eidx, Wr, br, v, out);
}

// round 3
// speedup vs baseline: 1.1150x; 1.1150x over previous
#include <cuda_runtime.h>
#include <math.h>
#include <cstdint>

#define N_NODES 10000
#define N_EDGES 160000
#define FDIM 128
#define NRBD 32
#define PHI_DIM 1024

// scratch (static device globals: allocation-free)
__device__ float g_h[N_NODES * FDIM];       // silu(s@W1+b1)
__device__ float g_phi[N_NODES * PHI_DIM];  // phi

// ---------------- packed f32x2 helpers (Blackwell FFMA2) ----------------
__device__ __forceinline__ unsigned long long pack2(float lo, float hi) {
    unsigned long long r;
    asm("mov.b64 %0, {%1, %2};" : "=l"(r) : "f"(lo), "f"(hi));
    return r;
}
__device__ __forceinline__ unsigned long long fma2(unsigned long long a,
                                                   unsigned long long b,
                                                   unsigned long long c) {
    unsigned long long d;
    asm("fma.rn.f32x2 %0, %1, %2, %3;" : "=l"(d) : "l"(a), "l"(b), "l"(c));
    return d;
}
__device__ __forceinline__ float2 unpack2(unsigned long long p) {
    float2 f;
    asm("mov.b64 {%0, %1}, %2;" : "=f"(f.x), "=f"(f.y) : "l"(p));
    return f;
}

// ---------------- init: out = concat(s, v) ----------------
__global__ void init_out_kernel(const float* __restrict__ s,
                                const float* __restrict__ v,
                                float* __restrict__ out) {
    int ns4 = (N_NODES * FDIM) / 4;
    int nv4 = (N_NODES * 3 * FDIM) / 4;
    int total4 = ns4 + nv4;
    for (int t = blockIdx.x * blockDim.x + threadIdx.x; t < total4;
         t += gridDim.x * blockDim.x) {
        float4 val = (t < ns4) ? ((const float4*)s)[t]
                               : ((const float4*)v)[t - ns4];
        ((float4*)out)[t] = val;
    }
}

// ---------------- SGEMM: C = A[M,K] @ B[K,N] + bias, optional SiLU ----------
// BM=BN=64, BK=16, TM=TN=4, 256 threads, FFMA2 inner loop.
template <bool SILU>
__global__ __launch_bounds__(256) void sgemm_kernel(
    const float* __restrict__ A, const float* __restrict__ B,
    const float* __restrict__ bias, float* __restrict__ C,
    int M, int N, int K) {
    __shared__ float As[16][68];  // transposed, padded
    __shared__ float Bs[16][64];

    int tid = threadIdx.x;
    int tx = tid % 16, ty = tid / 16;
    int bRow = blockIdx.y * 64, bCol = blockIdx.x * 64;
    int aRow = tid / 4, aCol = (tid % 4) * 4;
    int bRowL = tid / 16, bColL = (tid % 16) * 4;

    unsigned long long accp[4][2];
#pragma unroll
    for (int i = 0; i < 4; i++) {
        accp[i][0] = 0ULL;
        accp[i][1] = 0ULL;
    }

    for (int kt = 0; kt < K; kt += 16) {
        float4 a = make_float4(0.f, 0.f, 0.f, 0.f);
        int gRow = bRow + aRow;
        if (gRow < M) a = *(const float4*)(A + (size_t)gRow * K + kt + aCol);
        As[aCol + 0][aRow] = a.x;
        As[aCol + 1][aRow] = a.y;
        As[aCol + 2][aRow] = a.z;
        As[aCol + 3][aRow] = a.w;

        float4 b = *(const float4*)(B + (size_t)(kt + bRowL) * N + bCol + bColL);
        *(float4*)&Bs[bRowL][bColL] = b;
        __syncthreads();

#pragma unroll
        for (int k = 0; k < 16; ++k) {
            float4 bn = *(float4*)&Bs[k][tx * 4];
            unsigned long long pb0 = pack2(bn.x, bn.y);
            unsigned long long pb1 = pack2(bn.z, bn.w);
#pragma unroll
            for (int i = 0; i < 4; i++) {
                float rm = As[k][ty * 4 + i];
                unsigned long long rd = pack2(rm, rm);
                accp[i][0] = fma2(rd, pb0, accp[i][0]);
                accp[i][1] = fma2(rd, pb1, accp[i][1]);
            }
        }
        __syncthreads();
    }

#pragma unroll
    for (int i = 0; i < 4; i++) {
        int r = bRow + ty * 4 + i;
        if (r >= M) continue;
        float2 p0 = unpack2(accp[i][0]);
        float2 p1 = unpack2(accp[i][1]);
        float vals[4] = {p0.x, p0.y, p1.x, p1.y};
#pragma unroll
        for (int j = 0; j < 4; j++) {
            int c = bCol + tx * 4 + j;
            float val = vals[j] + bias[c];
            if (SILU) val = val / (1.0f + expf(-val));
            C[(size_t)r * N + c] = val;
        }
    }
}

// ---------------- fused edge kernel ----------------
// Per edge e:  rcomb = fc1*re1 + fc2*re2 + fc3*re3  (len 32)
//              W     = rcomb @ Wr + (fc1+fc2+fc3)*br  (len 1024)
//              x     = phi[j] * W   -> 8 chunks of 128
//              scatter-add into out_s[i], out_v[i] with unit-vector/cross math.
// 512 threads = 4 eslots x 128 features; each eslot register-blocks 8 edges.
// Mainloop uses packed fma.rn.f32x2 (2 FMAs/instr), pairing the chunk dim.
__global__ __launch_bounds__(512, 1) void edge_kernel(
    const float* __restrict__ re1, const float* __restrict__ re2,
    const float* __restrict__ re3, const float* __restrict__ fc1,
    const float* __restrict__ fc2, const float* __restrict__ fc3,
    const float* __restrict__ uv1, const float* __restrict__ uv2,
    const float* __restrict__ uv3, const int* __restrict__ eidx,
    const float* __restrict__ Wr, const float* __restrict__ br,
    const float* __restrict__ v, float* __restrict__ out) {
    extern __shared__ float smem[];
    float4* wrA = (float4*)smem;         // [32*128] chunks 0..3
    float4* wrB = wrA + NRBD * FDIM;     // [32*128] chunks 4..7
    float4* rc4 = wrB + NRBD * FDIM;     // [32 edges][8]  (rcomb as float4)
    float* uvs = (float*)(rc4 + 32 * 8); // [32][9]
    float* fcs = uvs + 32 * 9;           // [32]
    int* iis = (int*)(fcs + 32);         // [32]
    int* jjs = iis + 32;                 // [32]

    int tid = threadIdx.x;

    // one-time Wr load into transposed/split SMEM layout
    for (int idx = tid; idx < NRBD * PHI_DIM; idx += 512) {
        int k = idx >> 10;
        int col = idx & 1023;
        int c = col >> 7, ff = col & 127;
        float val = Wr[idx];
        float* dst = (c < 4) ? (float*)&wrA[k * FDIM + ff]
                             : (float*)&wrB[k * FDIM + ff];
        dst[c & 3] = val;
    }

    int ff = tid & 127;
    int eslot = tid >> 7;

    float brc[8];
#pragma unroll
    for (int c = 0; c < 8; c++) brc[c] = br[c * FDIM + ff];

    float* out_s = out;
    float* out_v = out + (size_t)N_NODES * FDIM;

    const int numTiles = N_EDGES / 32;
    for (int tile = blockIdx.x; tile < numTiles; tile += gridDim.x) {
        __syncthreads();  // protect smem staging vs previous iteration readers
        int eBase = tile * 32;

        // stage rcomb (32 edges x 32 k), float4-vectorized: 256 float4 / tile
        {
            float4* rcv = rc4;  // same layout: [e][8 float4]
            for (int t = tid; t < 32 * 8; t += 512) {
                int e = t >> 3;
                int ge = eBase + e;
                float c1 = fc1[ge], c2 = fc2[ge], c3 = fc3[ge];
                float4 a = ((const float4*)re1)[ge * 8 + (t & 7)];
                float4 b = ((const float4*)re2)[ge * 8 + (t & 7)];
                float4 c = ((const float4*)re3)[ge * 8 + (t & 7)];
                float4 r;
                r.x = a.x * c1 + b.x * c2 + c.x * c3;
                r.y = a.y * c1 + b.y * c2 + c.y * c3;
                r.z = a.z * c1 + b.z * c2 + c.z * c3;
                r.w = a.w * c1 + b.w * c2 + c.w * c3;
                rcv[t] = r;
            }
        }
        // per-edge metadata
        if (tid < 32) {
            int ge = eBase + tid;
            iis[tid] = eidx[ge];
            jjs[tid] = eidx[N_EDGES + ge];
            fcs[tid] = fc1[ge] + fc2[ge] + fc3[ge];
#pragma unroll
            for (int d = 0; d < 3; d++) {
                uvs[tid * 9 + d] = uv1[ge * 3 + d];
                uvs[tid * 9 + 3 + d] = uv2[ge * 3 + d];
                uvs[tid * 9 + 6 + d] = uv3[ge * 3 + d];
            }
        }
        __syncthreads();

        // W accumulators: 8 edges x 4 chunk-pairs, packed f32x2
        unsigned long long accp[8][4];
#pragma unroll
        for (int e = 0; e < 8; e++) {
            float fs = fcs[eslot * 8 + e];
            accp[e][0] = pack2(fs * brc[0], fs * brc[1]);
            accp[e][1] = pack2(fs * brc[2], fs * brc[3]);
            accp[e][2] = pack2(fs * brc[4], fs * brc[5]);
            accp[e][3] = pack2(fs * brc[6], fs * brc[7]);
        }

#pragma unroll
        for (int kk = 0; kk < 8; ++kk) {
            float4 r[8];
#pragma unroll
            for (int e = 0; e < 8; e++) r[e] = rc4[(eslot * 8 + e) * 8 + kk];
#pragma unroll
            for (int d = 0; d < 4; ++d) {
                int k = kk * 4 + d;
                float4 a = wrA[k * FDIM + ff];
                float4 b = wrB[k * FDIM + ff];
                unsigned long long pa0 = pack2(a.x, a.y);
                unsigned long long pa1 = pack2(a.z, a.w);
                unsigned long long pb0 = pack2(b.x, b.y);
                unsigned long long pb1 = pack2(b.z, b.w);
#pragma unroll
                for (int e = 0; e < 8; e++) {
                    float rv = (d == 0) ? r[e].x
                             : (d == 1) ? r[e].y
                             : (d == 2) ? r[e].z
                                        : r[e].w;
                    unsigned long long rp = pack2(rv, rv);
                    accp[e][0] = fma2(rp, pa0, accp[e][0]);
                    accp[e][1] = fma2(rp, pa1, accp[e][1]);
                    accp[e][2] = fma2(rp, pb0, accp[e][2]);
                    accp[e][3] = fma2(rp, pb1, accp[e][3]);
                }
            }
        }

        // epilogue: gather phi/v, vector + cross math, scatter-add
#pragma unroll
        for (int e = 0; e < 8; e++) {
            int le = eslot * 8 + e;
            int i = iis[le], j = jjs[le];
            float2 p0 = unpack2(accp[e][0]);
            float2 p1 = unpack2(accp[e][1]);
            float2 p2 = unpack2(accp[e][2]);
            float2 p3 = unpack2(accp[e][3]);
            const float* pj = g_phi + (size_t)j * PHI_DIM + ff;
            float x0 = p0.x * pj[0];
            float x1 = p0.y * pj[128];
            float x2 = p1.x * pj[256];
            float x3 = p1.y * pj[384];
            float x4 = p2.x * pj[512];
            float x5 = p2.y * pj[640];
            float x6 = p3.x * pj[768];
            float x7 = p3.y * pj[896];

            const float* vj = v + (size_t)j * (3 * FDIM) + ff;
            float v0 = vj[0], v1 = vj[128], v2 = vj[256];

            float u1x = uvs[le * 9 + 0], u1y = uvs[le * 9 + 1], u1z = uvs[le * 9 + 2];
            float u2x = uvs[le * 9 + 3], u2y = uvs[le * 9 + 4], u2z = uvs[le * 9 + 5];
            float u3x = uvs[le * 9 + 6], u3y = uvs[le * 9 + 7], u3z = uvs[le * 9 + 8];

            // cross(vj, u) = (v1*uz - v2*uy, v2*ux - v0*uz, v0*uy - v1*ux)
            float xv0 = v0 * x1 + x2 * u1x + x3 * u2x + x4 * u3x +
                        x5 * (v1 * u1z - v2 * u1y) +
                        x6 * (v1 * u2z - v2 * u2y) +
                        x7 * (v1 * u3z - v2 * u3y);
            float xv1 = v1 * x1 + x2 * u1y + x3 * u2y + x4 * u3y +
                        x5 * (v2 * u1x - v0 * u1z) +
                        x6 * (v2 * u2x - v0 * u2z) +
                        x7 * (v2 * u3x - v0 * u3z);
            float xv2 = v2 * x1 + x2 * u1z + x3 * u2z + x4 * u3z +
                        x5 * (v0 * u1y - v1 * u1x) +
                        x6 * (v0 * u2y - v1 * u2x) +
                        x7 * (v0 * u3y - v1 * u3x);

            atomicAdd(out_s + (size_t)i * FDIM + ff, x0);
            float* ov = out_v + (size_t)i * (3 * FDIM) + ff;
            atomicAdd(ov, xv0);
            atomicAdd(ov + 128, xv1);
            atomicAdd(ov + 256, xv2);
        }
    }
}

// ---------------- host ----------------
extern "C" void kernel_launch(void* const* d_in, const int* in_sizes, int n_in,
                              void* d_out, int out_size) {
    const float* s = (const float*)d_in[0];
    const float* v = (const float*)d_in[1];
    const float* re1 = (const float*)d_in[2];
    const float* re2 = (const float*)d_in[3];
    const float* re3 = (const float*)d_in[4];
    const float* fc1 = (const float*)d_in[5];
    const float* fc2 = (const float*)d_in[6];
    const float* fc3 = (const float*)d_in[7];
    const float* uv1 = (const float*)d_in[8];
    const float* uv2 = (const float*)d_in[9];
    const float* uv3 = (const float*)d_in[10];
    const int* eidx = (const int*)d_in[11];
    const float* W1 = (const float*)d_in[12];
    const float* b1 = (const float*)d_in[13];
    const float* W2 = (const float*)d_in[14];
    const float* b2 = (const float*)d_in[15];
    const float* Wr = (const float*)d_in[16];
    const float* br = (const float*)d_in[17];
    float* out = (float*)d_out;

    float *hptr, *phiptr;
    cudaGetSymbolAddress((void**)&hptr, g_h);
    cudaGetSymbolAddress((void**)&phiptr, g_phi);

    init_out_kernel<<<256, 256>>>(s, v, out);

    dim3 g1(FDIM / 64, (N_NODES + 63) / 64);
    sgemm_kernel<true><<<g1, 256>>>(s, W1, b1, hptr, N_NODES, FDIM, FDIM);

    dim3 g2(PHI_DIM / 64, (N_NODES + 63) / 64);
    sgemm_kernel<false><<<g2, 256>>>(hptr, W2, b2, phiptr, N_NODES, PHI_DIM, FDIM);

    int smem_bytes = (NRBD * FDIM * 2 + 32 * 8) * (int)sizeof(float4) +
                     (32 * 9 + 32) * (int)sizeof(float) + 32 * 2 * (int)sizeof(int);
    cudaFuncSetAttribute(edge_kernel,
                         cudaFuncAttributeMaxDynamicSharedMemorySize, smem_bytes);
    edge_kernel<<<148, 512, smem_bytes>>>(re1, re2, re3, fc1, fc2, fc3, uv1, uv2,
                                          uv3, eidx, Wr, br, v, out);
}